// round 5
// baseline (speedup 1.0000x reference)
#include <cuda_runtime.h>
#include <cuda_fp16.h>
#include <cstdint>
#include <cstddef>

#define TOK 16384
#define DD  2048
#define II  5632

// ---------------- scratch (device globals: no allocation allowed) ----------
__device__ __half g_W[6][(size_t)DD * II];      // fp16 weights: gate/up (D,I), down (I,D)
__device__ __half g_Xc[2][(size_t)TOK * DD];    // gathered activations per expert
__device__ __half g_H[2][(size_t)TOK * II];     // intermediate silu(g)*u per expert
__device__ int    g_idx[2][TOK];                // compacted token indices
__device__ int    g_cnt[2];                     // counts per expert

// ---------------- helpers --------------------------------------------------
__device__ __forceinline__ uint32_t smem_u32(const void* p) {
    return (uint32_t)__cvta_generic_to_shared(p);
}
__device__ __forceinline__ void cp16(void* dst, const void* src, bool pred) {
    uint32_t d = smem_u32(dst);
    int sz = pred ? 16 : 0;
    asm volatile("cp.async.cg.shared.global [%0], [%1], 16, %2;\n"
                 :: "r"(d), "l"(src), "r"(sz));
}
__device__ __forceinline__ void cp_commit() {
    asm volatile("cp.async.commit_group;\n");
}
__device__ __forceinline__ void cp_wait1() {
    asm volatile("cp.async.wait_group 1;\n");
}
__device__ __forceinline__ void ldsm4(uint32_t* r, const void* p) {
    uint32_t a = smem_u32(p);
    asm volatile("ldmatrix.sync.aligned.m8n8.x4.shared.b16 {%0,%1,%2,%3}, [%4];\n"
                 : "=r"(r[0]), "=r"(r[1]), "=r"(r[2]), "=r"(r[3]) : "r"(a));
}
__device__ __forceinline__ void ldsm4t(uint32_t* r, const void* p) {
    uint32_t a = smem_u32(p);
    asm volatile("ldmatrix.sync.aligned.m8n8.x4.trans.shared.b16 {%0,%1,%2,%3}, [%4];\n"
                 : "=r"(r[0]), "=r"(r[1]), "=r"(r[2]), "=r"(r[3]) : "r"(a));
}
__device__ __forceinline__ void mma16816(float* c, const uint32_t* a, const uint32_t* b) {
    asm volatile("mma.sync.aligned.m16n8k16.row.col.f32.f16.f16.f32 "
                 "{%0,%1,%2,%3}, {%4,%5,%6,%7}, {%8,%9}, {%0,%1,%2,%3};\n"
                 : "+f"(c[0]), "+f"(c[1]), "+f"(c[2]), "+f"(c[3])
                 : "r"(a[0]), "r"(a[1]), "r"(a[2]), "r"(a[3]), "r"(b[0]), "r"(b[1]));
}

// ---------------- kernel 1: mask decode + deterministic compaction --------
__global__ void prep_kernel(const unsigned char* mraw) {
    __shared__ int sf[4];
    __shared__ int scnt[256];
    __shared__ int soff[257];
    int t = threadIdx.x;
    if (t < 4) sf[t] = 0;
    __syncthreads();
    int f3F = 0, foff = 0, flo = 0, f3C = 0;
    for (int i = t * 64; i < t * 64 + 64; i++) {
        unsigned char b = mraw[i];
        if (b == 0x3F) f3F = 1;
        if (b == 0x3C) f3C = 1;
        if ((i & 3) && b) foff = 1;
        if (((i & 3) <= 1) && b) flo = 1;
    }
    if (f3F) atomicOr(&sf[0], 1);
    if (foff) atomicOr(&sf[1], 1);
    if (flo) atomicOr(&sf[2], 1);
    if (f3C) atomicOr(&sf[3], 1);
    __syncthreads();
    int mode;
    if (sf[0]) mode = sf[2] ? 3 : 2;
    else if (sf[3]) mode = 4;
    else if (sf[1]) mode = 0;
    else mode = 1;
    unsigned long long bits = 0;
    for (int i = 0; i < 64; i++) {
        int tok = t * 64 + i;
        bool g;
        if (mode == 0)      g = mraw[tok] != 0;
        else if (mode == 1) g = ((const int*)mraw)[tok] != 0;
        else if (mode == 2) g = ((const float*)mraw)[tok] != 0.0f;
        else                g = ((const unsigned short*)mraw)[tok] != 0;
        if (g) bits |= 1ull << i;
    }
    scnt[t] = __popcll(bits);
    __syncthreads();
    if (t == 0) {
        int a = 0;
        for (int i = 0; i < 256; i++) { soff[i] = a; a += scnt[i]; }
        g_cnt[1] = a;
        g_cnt[0] = TOK - a;
    }
    __syncthreads();
    int gp = soff[t];
    int up = t * 64 - gp;
    for (int i = 0; i < 64; i++) {
        int tok = t * 64 + i;
        if ((bits >> i) & 1) g_idx[1][gp++] = tok;
        else                 g_idx[0][up++] = tok;
    }
}

// ---------------- kernel 2: weight f32 -> f16 (same layout) ---------------
__global__ void cvt_w_kernel(const float* ug, const float* uu, const float* ud,
                             const float* gg, const float* gu, const float* gd) {
    const float* srcs[6] = { ug, uu, ud, gg, gu, gd };
    const float4* s = (const float4*)srcs[blockIdx.y];
    __half2* d = (__half2*)g_W[blockIdx.y];
    const size_t N4 = (size_t)DD * II / 4;
    for (size_t i = (size_t)blockIdx.x * blockDim.x + threadIdx.x; i < N4;
         i += (size_t)gridDim.x * blockDim.x) {
        float4 v = s[i];
        d[2 * i + 0] = __floats2half2_rn(v.x, v.y);
        d[2 * i + 1] = __floats2half2_rn(v.z, v.w);
    }
}

// ---------------- kernel 3: gather + convert X ----------------------------
__global__ void gather_kernel(const float* X) {
    int e = blockIdx.y;
    int slot = blockIdx.x;
    if (slot >= g_cnt[e]) return;
    const float4* s = (const float4*)(X + (size_t)g_idx[e][slot] * DD);
    __half2* d = (__half2*)(g_Xc[e] + (size_t)slot * DD);
    for (int i = threadIdx.x; i < DD / 4; i += blockDim.x) {
        float4 v = s[i];
        d[2 * i + 0] = __floats2half2_rn(v.x, v.y);
        d[2 * i + 1] = __floats2half2_rn(v.z, v.w);
    }
}

// ---------------- GEMM config ---------------------------------------------
// 256 threads, 8 warps, warp tile 64x64 (128 f32 accums). BK=64, 3 stages.
constexpr int BK  = 64;
constexpr int LDA = 72;          // halves per A smem row (64 + 8 pad); 144 B
constexpr int A_BYTES = 128 * LDA * 2;        // 18432
// gemm1: BN=128, two B matrices (gate, up), each [64][136]
constexpr int LDB1 = 136;                     // 272 B per row
constexpr int B1_BYTES = BK * LDB1 * 2;       // 17408
constexpr int STG1 = A_BYTES + 2 * B1_BYTES;  // 53248
constexpr int SMEM1 = 3 * STG1;               // 159744
// gemm2: BN=256, one B matrix [64][264]
constexpr int LDB2 = 264;                     // 528 B per row
constexpr int B2_BYTES = BK * LDB2 * 2;       // 33792
constexpr int STG2 = A_BYTES + B2_BYTES;      // 52224
constexpr int SMEM2 = 3 * STG2;               // 156672

// ---------------- kernel 4: fused gate/up GEMM + SiLU ---------------------
// CTA: 128 rows x 128 H-cols. Warps 0-3 gate, 4-7 up; each warp 64x64 tile.
__global__ __launch_bounds__(256, 1) void gemm1_kernel() {
    extern __shared__ char smem[];
    const int e = blockIdx.z;
    const int cnt = g_cnt[e];
    const int m0 = blockIdx.x * 128;
    if (m0 >= cnt) return;
    const int n0 = blockIdx.y * 128;
    const __half* A  = g_Xc[e];
    const __half* Bg = g_W[e ? 3 : 0];
    const __half* Bu = g_W[e ? 4 : 1];
    const int t = threadIdx.x;
    const int wid = t >> 5, lane = t & 31;
    const int gu = wid >> 2;                 // 0 = gate, 1 = up
    const int wm = (wid >> 1) & 1;           // 64-row slab
    const int wn = wid & 1;                  // 64-col slab

    auto load_stage = [&](int kb, int st) {
        char* base = smem + st * STG1;
        #pragma unroll
        for (int i = 0; i < 4; i++) {        // A: 128 rows x 8 chunks = 1024
            int id = t + i * 256;
            int r = id >> 3, c = id & 7;
            cp16(base + r * (LDA * 2) + c * 16,
                 A + (size_t)(m0 + r) * DD + kb * BK + c * 8, (m0 + r) < cnt);
        }
        #pragma unroll
        for (int i = 0; i < 4; i++) {        // Bg & Bu: each 64 rows x 16 chunks
            int id = t + i * 256;
            int r = id >> 4, c = id & 15;
            size_t go = (size_t)(kb * BK + r) * II + n0 + c * 8;
            char* bb = base + A_BYTES + r * (LDB1 * 2) + c * 16;
            cp16(bb, Bg + go, true);
            cp16(bb + B1_BYTES, Bu + go, true);
        }
        cp_commit();
    };

    float acc[4][8][4];
    #pragma unroll
    for (int mi = 0; mi < 4; mi++)
        #pragma unroll
        for (int ni = 0; ni < 8; ni++)
            #pragma unroll
            for (int k = 0; k < 4; k++) acc[mi][ni][k] = 0.f;

    const int KB = DD / BK;   // 32
    load_stage(0, 0);
    load_stage(1, 1);

    const int lr = lane % 16, lc = (lane / 16) * 8;

    for (int kb = 0; kb < KB; kb++) {
        int st = kb % 3;
        cp_wait1();
        __syncthreads();
        if (kb + 2 < KB) load_stage(kb + 2, (kb + 2) % 3); else cp_commit();

        char* base = smem + st * STG1;
        const __half* At = (const __half*)base;
        const __half* Bt = (const __half*)(base + A_BYTES + gu * B1_BYTES);
        #pragma unroll
        for (int ks = 0; ks < 4; ks++) {
            uint32_t a[4][4];
            #pragma unroll
            for (int mi = 0; mi < 4; mi++)
                ldsm4(a[mi], At + (wm * 64 + mi * 16 + lr) * LDA + ks * 16 + lc);
            uint32_t b[4][4];
            #pragma unroll
            for (int np = 0; np < 4; np++)
                ldsm4t(b[np], Bt + (ks * 16 + lr) * LDB1 + wn * 64 + np * 16 + lc);
            #pragma unroll
            for (int mi = 0; mi < 4; mi++)
                #pragma unroll
                for (int ni = 0; ni < 8; ni++)
                    mma16816(acc[mi][ni], a[mi], &b[ni >> 1][(ni & 1) * 2]);
        }
    }

    // epilogue: gate warps stage g (f32) in smem; up warps combine + store H
    __syncthreads();
    float* stg = (float*)smem;               // 128 x 132
    const int r4 = lane >> 2, c2 = (lane & 3) * 2;
    if (gu == 0) {
        #pragma unroll
        for (int mi = 0; mi < 4; mi++)
            #pragma unroll
            for (int h = 0; h < 2; h++) {
                int row = wm * 64 + mi * 16 + h * 8 + r4;
                #pragma unroll
                for (int ni = 0; ni < 8; ni++) {
                    int col = wn * 64 + ni * 8 + c2;
                    stg[row * 132 + col]     = acc[mi][ni][h * 2 + 0];
                    stg[row * 132 + col + 1] = acc[mi][ni][h * 2 + 1];
                }
            }
    }
    __syncthreads();
    if (gu == 1) {
        #pragma unroll
        for (int mi = 0; mi < 4; mi++)
            #pragma unroll
            for (int h = 0; h < 2; h++) {
                int row = wm * 64 + mi * 16 + h * 8 + r4;
                int slot = m0 + row;
                if (slot < cnt) {
                    __half2* dst = (__half2*)(g_H[e] + (size_t)slot * II + n0);
                    #pragma unroll
                    for (int ni = 0; ni < 8; ni++) {
                        int col = wn * 64 + ni * 8 + c2;
                        float g0 = stg[row * 132 + col];
                        float g1 = stg[row * 132 + col + 1];
                        float u0 = acc[mi][ni][h * 2 + 0];
                        float u1 = acc[mi][ni][h * 2 + 1];
                        float h0 = g0 / (1.0f + expf(-g0)) * u0;
                        float h1 = g1 / (1.0f + expf(-g1)) * u1;
                        dst[col >> 1] = __floats2half2_rn(h0, h1);
                    }
                }
            }
    }
}

// ---------------- kernel 5: down GEMM + scatter ---------------------------
// CTA: 128 rows x 256 out-cols. 8 warps: wm=wid&1 (64-row), wn=wid>>1 (64-col).
__global__ __launch_bounds__(256, 1) void gemm2_kernel(float* out) {
    extern __shared__ char smem[];
    const int e = blockIdx.z;
    const int cnt = g_cnt[e];
    const int m0 = blockIdx.x * 128;
    if (m0 >= cnt) return;
    const int n0 = blockIdx.y * 256;
    const __half* A  = g_H[e];
    const __half* Bd = g_W[e ? 5 : 2];
    const int t = threadIdx.x;
    const int wid = t >> 5, lane = t & 31;
    const int wm = wid & 1;
    const int wn = wid >> 1;                 // 0..3

    auto load_stage = [&](int kb, int st) {
        char* base = smem + st * STG2;
        #pragma unroll
        for (int i = 0; i < 4; i++) {        // A: 1024 chunks
            int id = t + i * 256;
            int r = id >> 3, c = id & 7;
            cp16(base + r * (LDA * 2) + c * 16,
                 A + (size_t)(m0 + r) * II + kb * BK + c * 8, (m0 + r) < cnt);
        }
        #pragma unroll
        for (int i = 0; i < 8; i++) {        // B: 64 rows x 32 chunks = 2048
            int id = t + i * 256;
            int r = id >> 5, c = id & 31;
            cp16(base + A_BYTES + r * (LDB2 * 2) + c * 16,
                 Bd + (size_t)(kb * BK + r) * DD + n0 + c * 8, true);
        }
        cp_commit();
    };

    float acc[4][8][4];
    #pragma unroll
    for (int mi = 0; mi < 4; mi++)
        #pragma unroll
        for (int ni = 0; ni < 8; ni++)
            #pragma unroll
            for (int k = 0; k < 4; k++) acc[mi][ni][k] = 0.f;

    const int KB = II / BK;   // 88
    load_stage(0, 0);
    load_stage(1, 1);

    const int lr = lane % 16, lc = (lane / 16) * 8;

    for (int kb = 0; kb < KB; kb++) {
        int st = kb % 3;
        cp_wait1();
        __syncthreads();
        if (kb + 2 < KB) load_stage(kb + 2, (kb + 2) % 3); else cp_commit();

        char* base = smem + st * STG2;
        const __half* At = (const __half*)base;
        const __half* Bt = (const __half*)(base + A_BYTES);
        #pragma unroll
        for (int ks = 0; ks < 4; ks++) {
            uint32_t a[4][4];
            #pragma unroll
            for (int mi = 0; mi < 4; mi++)
                ldsm4(a[mi], At + (wm * 64 + mi * 16 + lr) * LDA + ks * 16 + lc);
            uint32_t b[4][4];
            #pragma unroll
            for (int np = 0; np < 4; np++)
                ldsm4t(b[np], Bt + (ks * 16 + lr) * LDB2 + wn * 64 + np * 16 + lc);
            #pragma unroll
            for (int mi = 0; mi < 4; mi++)
                #pragma unroll
                for (int ni = 0; ni < 8; ni++)
                    mma16816(acc[mi][ni], a[mi], &b[ni >> 1][(ni & 1) * 2]);
        }
    }

    // epilogue: scatter f32 to original token rows
    const int r4 = lane >> 2, c2 = (lane & 3) * 2;
    #pragma unroll
    for (int mi = 0; mi < 4; mi++)
        #pragma unroll
        for (int h = 0; h < 2; h++) {
            int row = wm * 64 + mi * 16 + h * 8 + r4;
            int slot = m0 + row;
            if (slot < cnt) {
                int token = g_idx[e][slot];
                float2* dst = (float2*)(out + (size_t)token * DD + n0);
                #pragma unroll
                for (int ni = 0; ni < 8; ni++) {
                    int col = wn * 64 + ni * 8 + c2;
                    dst[col >> 1] = make_float2(acc[mi][ni][h * 2 + 0],
                                                acc[mi][ni][h * 2 + 1]);
                }
            }
        }
}

// ---------------- host launcher -------------------------------------------
extern "C" void kernel_launch(void* const* d_in, const int* in_sizes, int n_in,
                              void* d_out, int out_size) {
    const float* X = (const float*)d_in[0];
    const unsigned char* M = (const unsigned char*)d_in[1];
    const float* ug = (const float*)d_in[2];
    const float* uu = (const float*)d_in[3];
    const float* ud = (const float*)d_in[4];
    const float* gg = (const float*)d_in[5];
    const float* gu = (const float*)d_in[6];
    const float* gd = (const float*)d_in[7];
    float* out = (float*)d_out;

    cudaFuncSetAttribute(gemm1_kernel, cudaFuncAttributeMaxDynamicSharedMemorySize, SMEM1);
    cudaFuncSetAttribute(gemm2_kernel, cudaFuncAttributeMaxDynamicSharedMemorySize, SMEM2);

    prep_kernel<<<1, 256>>>(M);
    cvt_w_kernel<<<dim3(2048, 6), 256>>>(ug, uu, ud, gg, gu, gd);
    gather_kernel<<<dim3(TOK, 2), 128>>>(X);
    gemm1_kernel<<<dim3(TOK / 128, II / 128, 2), 256, SMEM1>>>();
    gemm2_kernel<<<dim3(TOK / 128, DD / 256, 2), 256, SMEM2>>>(out);
}

// round 6
// speedup vs baseline: 1.0840x; 1.0840x over previous
#include <cuda_runtime.h>
#include <cuda_fp16.h>
#include <cstdint>
#include <cstddef>

#define TOK 16384
#define DD  2048
#define II  5632

// ---------------- scratch (device globals: no allocation allowed) ----------
__device__ __half g_W[6][(size_t)DD * II];      // fp16 weights: gate/up (D,I), down (I,D)
__device__ __half g_Xc[2][(size_t)TOK * DD];    // gathered activations per expert
__device__ __half g_H[2][(size_t)TOK * II];     // intermediate silu(g)*u per expert
__device__ int    g_idx[2][TOK];                // compacted token indices
__device__ int    g_cnt[2];                     // counts per expert

// ---------------- helpers --------------------------------------------------
__device__ __forceinline__ uint32_t smem_u32(const void* p) {
    return (uint32_t)__cvta_generic_to_shared(p);
}
__device__ __forceinline__ void cp16(void* dst, const void* src, bool pred) {
    uint32_t d = smem_u32(dst);
    int sz = pred ? 16 : 0;
    asm volatile("cp.async.cg.shared.global [%0], [%1], 16, %2;\n"
                 :: "r"(d), "l"(src), "r"(sz));
}
__device__ __forceinline__ void cp_commit() {
    asm volatile("cp.async.commit_group;\n");
}
__device__ __forceinline__ void cp_wait2() {
    asm volatile("cp.async.wait_group 2;\n");
}
__device__ __forceinline__ void ldsm4(uint32_t* r, const void* p) {
    uint32_t a = smem_u32(p);
    asm volatile("ldmatrix.sync.aligned.m8n8.x4.shared.b16 {%0,%1,%2,%3}, [%4];\n"
                 : "=r"(r[0]), "=r"(r[1]), "=r"(r[2]), "=r"(r[3]) : "r"(a));
}
__device__ __forceinline__ void ldsm4t(uint32_t* r, const void* p) {
    uint32_t a = smem_u32(p);
    asm volatile("ldmatrix.sync.aligned.m8n8.x4.trans.shared.b16 {%0,%1,%2,%3}, [%4];\n"
                 : "=r"(r[0]), "=r"(r[1]), "=r"(r[2]), "=r"(r[3]) : "r"(a));
}
__device__ __forceinline__ void mma16816(float* c, const uint32_t* a, const uint32_t* b) {
    asm volatile("mma.sync.aligned.m16n8k16.row.col.f32.f16.f16.f32 "
                 "{%0,%1,%2,%3}, {%4,%5,%6,%7}, {%8,%9}, {%0,%1,%2,%3};\n"
                 : "+f"(c[0]), "+f"(c[1]), "+f"(c[2]), "+f"(c[3])
                 : "r"(a[0]), "r"(a[1]), "r"(a[2]), "r"(a[3]), "r"(b[0]), "r"(b[1]));
}

// ---------------- kernel 1: mask decode + deterministic compaction --------
__global__ void prep_kernel(const unsigned char* mraw) {
    __shared__ int sf[4];
    __shared__ int scnt[256];
    __shared__ int soff[257];
    int t = threadIdx.x;
    if (t < 4) sf[t] = 0;
    __syncthreads();
    int f3F = 0, foff = 0, flo = 0, f3C = 0;
    for (int i = t * 64; i < t * 64 + 64; i++) {
        unsigned char b = mraw[i];
        if (b == 0x3F) f3F = 1;
        if (b == 0x3C) f3C = 1;
        if ((i & 3) && b) foff = 1;
        if (((i & 3) <= 1) && b) flo = 1;
    }
    if (f3F) atomicOr(&sf[0], 1);
    if (foff) atomicOr(&sf[1], 1);
    if (flo) atomicOr(&sf[2], 1);
    if (f3C) atomicOr(&sf[3], 1);
    __syncthreads();
    int mode;
    if (sf[0]) mode = sf[2] ? 3 : 2;
    else if (sf[3]) mode = 4;
    else if (sf[1]) mode = 0;
    else mode = 1;
    unsigned long long bits = 0;
    for (int i = 0; i < 64; i++) {
        int tok = t * 64 + i;
        bool g;
        if (mode == 0)      g = mraw[tok] != 0;
        else if (mode == 1) g = ((const int*)mraw)[tok] != 0;
        else if (mode == 2) g = ((const float*)mraw)[tok] != 0.0f;
        else                g = ((const unsigned short*)mraw)[tok] != 0;
        if (g) bits |= 1ull << i;
    }
    scnt[t] = __popcll(bits);
    __syncthreads();
    if (t == 0) {
        int a = 0;
        for (int i = 0; i < 256; i++) { soff[i] = a; a += scnt[i]; }
        g_cnt[1] = a;
        g_cnt[0] = TOK - a;
    }
    __syncthreads();
    int gp = soff[t];
    int up = t * 64 - gp;
    for (int i = 0; i < 64; i++) {
        int tok = t * 64 + i;
        if ((bits >> i) & 1) g_idx[1][gp++] = tok;
        else                 g_idx[0][up++] = tok;
    }
}

// ---------------- kernel 2: weight f32 -> f16 (same layout) ---------------
__global__ void cvt_w_kernel(const float* ug, const float* uu, const float* ud,
                             const float* gg, const float* gu, const float* gd) {
    const float* srcs[6] = { ug, uu, ud, gg, gu, gd };
    const float4* s = (const float4*)srcs[blockIdx.y];
    __half2* d = (__half2*)g_W[blockIdx.y];
    const size_t N4 = (size_t)DD * II / 4;
    for (size_t i = (size_t)blockIdx.x * blockDim.x + threadIdx.x; i < N4;
         i += (size_t)gridDim.x * blockDim.x) {
        float4 v = s[i];
        d[2 * i + 0] = __floats2half2_rn(v.x, v.y);
        d[2 * i + 1] = __floats2half2_rn(v.z, v.w);
    }
}

// ---------------- kernel 3: gather + convert X ----------------------------
__global__ void gather_kernel(const float* X) {
    int e = blockIdx.y;
    int slot = blockIdx.x;
    if (slot >= g_cnt[e]) return;
    const float4* s = (const float4*)(X + (size_t)g_idx[e][slot] * DD);
    __half2* d = (__half2*)(g_Xc[e] + (size_t)slot * DD);
    for (int i = threadIdx.x; i < DD / 4; i += blockDim.x) {
        float4 v = s[i];
        d[2 * i + 0] = __floats2half2_rn(v.x, v.y);
        d[2 * i + 1] = __floats2half2_rn(v.z, v.w);
    }
}

// ---------------- GEMM config ---------------------------------------------
// 512 threads, 16 warps. BK=64, 4 stages.
constexpr int BK  = 64;
constexpr int STAGES = 4;
constexpr int LDA = 72;          // halves per A smem row (64 + 8 pad); 144 B
constexpr int A_BYTES = 128 * LDA * 2;        // 18432
// gemm1: BN=128, two B matrices (gate, up), each [64][136]
constexpr int LDB1 = 136;                     // 272 B per row
constexpr int B1_BYTES = BK * LDB1 * 2;       // 17408
constexpr int STG1 = A_BYTES + 2 * B1_BYTES;  // 53248
constexpr int SMEM1 = STAGES * STG1;          // 212992
// gemm2: BN=256, one B matrix [64][264]
constexpr int LDB2 = 264;                     // 528 B per row
constexpr int B2_BYTES = BK * LDB2 * 2;       // 33792
constexpr int STG2 = A_BYTES + B2_BYTES;      // 52224
constexpr int SMEM2 = STAGES * STG2;          // 208896

// ---------------- kernel 4: fused gate/up GEMM + SiLU ---------------------
// CTA: 128 rows x 128 H-cols. Warps 0-7 compute gate, warps 8-15 compute up.
// Each warp: 32x64 tile of ONE output => 64 f32 accums.
__global__ __launch_bounds__(512, 1) void gemm1_kernel() {
    extern __shared__ char smem[];
    const int e = blockIdx.z;
    const int cnt = g_cnt[e];
    const int m0 = blockIdx.x * 128;
    if (m0 >= cnt) return;
    const int n0 = blockIdx.y * 128;
    const __half* A  = g_Xc[e];
    const __half* Bg = g_W[e ? 3 : 0];
    const __half* Bu = g_W[e ? 4 : 1];
    const int t = threadIdx.x;
    const int wid = t >> 5, lane = t & 31;
    const int gu = wid >> 3;                 // 0 = gate, 1 = up
    const int wm = (wid & 7) >> 1;           // 0..3  (32-row slab)
    const int wn = wid & 1;                  // 0..1  (64-col slab)
    const int kofs = (wid >> 2) & 3;         // de-phase warps sharing an SMSP

    auto load_stage = [&](int kb, int st) {
        char* base = smem + st * STG1;
        #pragma unroll
        for (int i = 0; i < 2; i++) {        // A: 128 rows x 8 chunks = 1024
            int id = t + i * 512;
            int r = id >> 3, c = id & 7;
            cp16(base + r * (LDA * 2) + c * 16,
                 A + (size_t)(m0 + r) * DD + kb * BK + c * 8, (m0 + r) < cnt);
        }
        #pragma unroll
        for (int i = 0; i < 2; i++) {        // Bg & Bu: each 64 rows x 16 chunks = 1024
            int id = t + i * 512;
            int r = id >> 4, c = id & 15;
            size_t go = (size_t)(kb * BK + r) * II + n0 + c * 8;
            char* bb = base + A_BYTES + r * (LDB1 * 2) + c * 16;
            cp16(bb, Bg + go, true);
            cp16(bb + B1_BYTES, Bu + go, true);
        }
        cp_commit();
    };

    float acc[2][8][4];
    #pragma unroll
    for (int mi = 0; mi < 2; mi++)
        #pragma unroll
        for (int ni = 0; ni < 8; ni++)
            #pragma unroll
            for (int k = 0; k < 4; k++) acc[mi][ni][k] = 0.f;

    const int KB = DD / BK;   // 32
    load_stage(0, 0);
    load_stage(1, 1);
    load_stage(2, 2);

    const int lr = lane % 16, lc = (lane / 16) * 8;

    for (int kb = 0; kb < KB; kb++) {
        int st = kb % STAGES;
        cp_wait2();
        __syncthreads();
        if (kb + 3 < KB) load_stage(kb + 3, (kb + 3) % STAGES); else cp_commit();

        char* base = smem + st * STG1;
        const __half* At = (const __half*)base;
        const __half* Bt = (const __half*)(base + A_BYTES + gu * B1_BYTES);
        #pragma unroll
        for (int ksi = 0; ksi < 4; ksi++) {
            int ks = (ksi + kofs) & 3;
            uint32_t a[2][4];
            #pragma unroll
            for (int mi = 0; mi < 2; mi++)
                ldsm4(a[mi], At + (wm * 32 + mi * 16 + lr) * LDA + ks * 16 + lc);
            uint32_t b[4][4];
            #pragma unroll
            for (int np = 0; np < 4; np++)
                ldsm4t(b[np], Bt + (ks * 16 + lr) * LDB1 + wn * 64 + np * 16 + lc);
            #pragma unroll
            for (int mi = 0; mi < 2; mi++)
                #pragma unroll
                for (int ni = 0; ni < 8; ni++)
                    mma16816(acc[mi][ni], a[mi], &b[ni >> 1][(ni & 1) * 2]);
        }
    }

    // epilogue: gate warps stage g (f32) in smem; up warps combine + store H
    __syncthreads();
    float* stg = (float*)smem;               // 128 x 132
    const int r4 = lane >> 2, c2 = (lane & 3) * 2;
    if (gu == 0) {
        #pragma unroll
        for (int mi = 0; mi < 2; mi++)
            #pragma unroll
            for (int h = 0; h < 2; h++) {
                int row = wm * 32 + mi * 16 + h * 8 + r4;
                #pragma unroll
                for (int ni = 0; ni < 8; ni++) {
                    int col = wn * 64 + ni * 8 + c2;
                    stg[row * 132 + col]     = acc[mi][ni][h * 2 + 0];
                    stg[row * 132 + col + 1] = acc[mi][ni][h * 2 + 1];
                }
            }
    }
    __syncthreads();
    if (gu == 1) {
        #pragma unroll
        for (int mi = 0; mi < 2; mi++)
            #pragma unroll
            for (int h = 0; h < 2; h++) {
                int row = wm * 32 + mi * 16 + h * 8 + r4;
                int slot = m0 + row;
                if (slot < cnt) {
                    __half2* dst = (__half2*)(g_H[e] + (size_t)slot * II + n0);
                    #pragma unroll
                    for (int ni = 0; ni < 8; ni++) {
                        int col = wn * 64 + ni * 8 + c2;
                        float g0 = stg[row * 132 + col];
                        float g1 = stg[row * 132 + col + 1];
                        float u0 = acc[mi][ni][h * 2 + 0];
                        float u1 = acc[mi][ni][h * 2 + 1];
                        float h0 = g0 / (1.0f + expf(-g0)) * u0;
                        float h1 = g1 / (1.0f + expf(-g1)) * u1;
                        dst[col >> 1] = __floats2half2_rn(h0, h1);
                    }
                }
            }
    }
}

// ---------------- kernel 5: down GEMM + scatter ---------------------------
// CTA: 128 rows x 256 out-cols. 16 warps: wm=wid%4 (rows), wn=wid/4 (64-col slab).
__global__ __launch_bounds__(512, 1) void gemm2_kernel(float* out) {
    extern __shared__ char smem[];
    const int e = blockIdx.z;
    const int cnt = g_cnt[e];
    const int m0 = blockIdx.x * 128;
    if (m0 >= cnt) return;
    const int n0 = blockIdx.y * 256;
    const __half* A  = g_H[e];
    const __half* Bd = g_W[e ? 5 : 2];
    const int t = threadIdx.x;
    const int wid = t >> 5, lane = t & 31;
    const int wm = wid & 3;
    const int wn = wid >> 2;                 // 0..3
    const int kofs = (wid >> 2) & 3;         // de-phase warps sharing an SMSP

    auto load_stage = [&](int kb, int st) {
        char* base = smem + st * STG2;
        #pragma unroll
        for (int i = 0; i < 2; i++) {        // A: 1024 chunks
            int id = t + i * 512;
            int r = id >> 3, c = id & 7;
            cp16(base + r * (LDA * 2) + c * 16,
                 A + (size_t)(m0 + r) * II + kb * BK + c * 8, (m0 + r) < cnt);
        }
        #pragma unroll
        for (int i = 0; i < 4; i++) {        // B: 64 rows x 32 chunks = 2048
            int id = t + i * 512;
            int r = id >> 5, c = id & 31;
            cp16(base + A_BYTES + r * (LDB2 * 2) + c * 16,
                 Bd + (size_t)(kb * BK + r) * DD + n0 + c * 8, true);
        }
        cp_commit();
    };

    float acc[2][8][4];
    #pragma unroll
    for (int mi = 0; mi < 2; mi++)
        #pragma unroll
        for (int ni = 0; ni < 8; ni++)
            #pragma unroll
            for (int k = 0; k < 4; k++) acc[mi][ni][k] = 0.f;

    const int KB = II / BK;   // 88
    load_stage(0, 0);
    load_stage(1, 1);
    load_stage(2, 2);

    const int lr = lane % 16, lc = (lane / 16) * 8;

    for (int kb = 0; kb < KB; kb++) {
        int st = kb % STAGES;
        cp_wait2();
        __syncthreads();
        if (kb + 3 < KB) load_stage(kb + 3, (kb + 3) % STAGES); else cp_commit();

        char* base = smem + st * STG2;
        const __half* At = (const __half*)base;
        const __half* Bt = (const __half*)(base + A_BYTES);
        #pragma unroll
        for (int ksi = 0; ksi < 4; ksi++) {
            int ks = (ksi + kofs) & 3;
            uint32_t a[2][4];
            #pragma unroll
            for (int mi = 0; mi < 2; mi++)
                ldsm4(a[mi], At + (wm * 32 + mi * 16 + lr) * LDA + ks * 16 + lc);
            uint32_t b[4][4];
            #pragma unroll
            for (int np = 0; np < 4; np++)
                ldsm4t(b[np], Bt + (ks * 16 + lr) * LDB2 + wn * 64 + np * 16 + lc);
            #pragma unroll
            for (int mi = 0; mi < 2; mi++)
                #pragma unroll
                for (int ni = 0; ni < 8; ni++)
                    mma16816(acc[mi][ni], a[mi], &b[ni >> 1][(ni & 1) * 2]);
        }
    }

    // epilogue: scatter f32 to original token rows
    const int r4 = lane >> 2, c2 = (lane & 3) * 2;
    #pragma unroll
    for (int mi = 0; mi < 2; mi++)
        #pragma unroll
        for (int h = 0; h < 2; h++) {
            int row = wm * 32 + mi * 16 + h * 8 + r4;
            int slot = m0 + row;
            if (slot < cnt) {
                int token = g_idx[e][slot];
                float2* dst = (float2*)(out + (size_t)token * DD + n0);
                #pragma unroll
                for (int ni = 0; ni < 8; ni++) {
                    int col = wn * 64 + ni * 8 + c2;
                    dst[col >> 1] = make_float2(acc[mi][ni][h * 2 + 0],
                                                acc[mi][ni][h * 2 + 1]);
                }
            }
        }
}

// ---------------- host launcher -------------------------------------------
extern "C" void kernel_launch(void* const* d_in, const int* in_sizes, int n_in,
                              void* d_out, int out_size) {
    const float* X = (const float*)d_in[0];
    const unsigned char* M = (const unsigned char*)d_in[1];
    const float* ug = (const float*)d_in[2];
    const float* uu = (const float*)d_in[3];
    const float* ud = (const float*)d_in[4];
    const float* gg = (const float*)d_in[5];
    const float* gu = (const float*)d_in[6];
    const float* gd = (const float*)d_in[7];
    float* out = (float*)d_out;

    cudaFuncSetAttribute(gemm1_kernel, cudaFuncAttributeMaxDynamicSharedMemorySize, SMEM1);
    cudaFuncSetAttribute(gemm2_kernel, cudaFuncAttributeMaxDynamicSharedMemorySize, SMEM2);

    prep_kernel<<<1, 256>>>(M);
    cvt_w_kernel<<<dim3(2048, 6), 256>>>(ug, uu, ud, gg, gu, gd);
    gather_kernel<<<dim3(TOK, 2), 128>>>(X);
    gemm1_kernel<<<dim3(TOK / 128, II / 128, 2), 512, SMEM1>>>();
    gemm2_kernel<<<dim3(TOK / 128, DD / 256, 2), 512, SMEM2>>>(out);
}

// round 7
// speedup vs baseline: 1.0907x; 1.0062x over previous
#include <cuda_runtime.h>
#include <cuda_fp16.h>
#include <cstdint>
#include <cstddef>

#define TOK 16384
#define DD  2048
#define II  5632

// ---------------- scratch (device globals: no allocation allowed) ----------
__device__ __half g_W[6][(size_t)DD * II];      // fp16 weights: gate/up (D,I), down (I,D)
__device__ __half g_Xc[2][(size_t)TOK * DD];    // gathered activations per expert
__device__ __half g_H[2][(size_t)TOK * II];     // intermediate silu(g)*u per expert
__device__ int    g_idx[2][TOK];                // compacted token indices
__device__ int    g_cnt[2];                     // counts per expert

// ---------------- helpers --------------------------------------------------
__device__ __forceinline__ uint32_t smem_u32(const void* p) {
    return (uint32_t)__cvta_generic_to_shared(p);
}
__device__ __forceinline__ void cp16(void* dst, const void* src, bool pred) {
    uint32_t d = smem_u32(dst);
    int sz = pred ? 16 : 0;
    asm volatile("cp.async.cg.shared.global [%0], [%1], 16, %2;\n"
                 :: "r"(d), "l"(src), "r"(sz));
}
__device__ __forceinline__ void cp_commit() {
    asm volatile("cp.async.commit_group;\n");
}
__device__ __forceinline__ void cp_wait1() {
    asm volatile("cp.async.wait_group 1;\n");
}
__device__ __forceinline__ void ldsm4(uint32_t* r, const void* p) {
    uint32_t a = smem_u32(p);
    asm volatile("ldmatrix.sync.aligned.m8n8.x4.shared.b16 {%0,%1,%2,%3}, [%4];\n"
                 : "=r"(r[0]), "=r"(r[1]), "=r"(r[2]), "=r"(r[3]) : "r"(a));
}
__device__ __forceinline__ void ldsm4t(uint32_t* r, const void* p) {
    uint32_t a = smem_u32(p);
    asm volatile("ldmatrix.sync.aligned.m8n8.x4.trans.shared.b16 {%0,%1,%2,%3}, [%4];\n"
                 : "=r"(r[0]), "=r"(r[1]), "=r"(r[2]), "=r"(r[3]) : "r"(a));
}
__device__ __forceinline__ void mma16816(float* c, const uint32_t* a, const uint32_t* b) {
    asm volatile("mma.sync.aligned.m16n8k16.row.col.f32.f16.f16.f32 "
                 "{%0,%1,%2,%3}, {%4,%5,%6,%7}, {%8,%9}, {%0,%1,%2,%3};\n"
                 : "+f"(c[0]), "+f"(c[1]), "+f"(c[2]), "+f"(c[3])
                 : "r"(a[0]), "r"(a[1]), "r"(a[2]), "r"(a[3]), "r"(b[0]), "r"(b[1]));
}

// ---------------- kernel 1: mask decode + deterministic compaction --------
__global__ void prep_kernel(const unsigned char* mraw) {
    __shared__ int sf[4];
    __shared__ int scnt[256];
    __shared__ int soff[257];
    int t = threadIdx.x;
    if (t < 4) sf[t] = 0;
    __syncthreads();
    int f3F = 0, foff = 0, flo = 0, f3C = 0;
    for (int i = t * 64; i < t * 64 + 64; i++) {
        unsigned char b = mraw[i];
        if (b == 0x3F) f3F = 1;
        if (b == 0x3C) f3C = 1;
        if ((i & 3) && b) foff = 1;
        if (((i & 3) <= 1) && b) flo = 1;
    }
    if (f3F) atomicOr(&sf[0], 1);
    if (foff) atomicOr(&sf[1], 1);
    if (flo) atomicOr(&sf[2], 1);
    if (f3C) atomicOr(&sf[3], 1);
    __syncthreads();
    int mode;
    if (sf[0]) mode = sf[2] ? 3 : 2;
    else if (sf[3]) mode = 4;
    else if (sf[1]) mode = 0;
    else mode = 1;
    unsigned long long bits = 0;
    for (int i = 0; i < 64; i++) {
        int tok = t * 64 + i;
        bool g;
        if (mode == 0)      g = mraw[tok] != 0;
        else if (mode == 1) g = ((const int*)mraw)[tok] != 0;
        else if (mode == 2) g = ((const float*)mraw)[tok] != 0.0f;
        else                g = ((const unsigned short*)mraw)[tok] != 0;
        if (g) bits |= 1ull << i;
    }
    scnt[t] = __popcll(bits);
    __syncthreads();
    if (t == 0) {
        int a = 0;
        for (int i = 0; i < 256; i++) { soff[i] = a; a += scnt[i]; }
        g_cnt[1] = a;
        g_cnt[0] = TOK - a;
    }
    __syncthreads();
    int gp = soff[t];
    int up = t * 64 - gp;
    for (int i = 0; i < 64; i++) {
        int tok = t * 64 + i;
        if ((bits >> i) & 1) g_idx[1][gp++] = tok;
        else                 g_idx[0][up++] = tok;
    }
}

// ---------------- kernel 2: weight f32 -> f16 (same layout) ---------------
__global__ void cvt_w_kernel(const float* ug, const float* uu, const float* ud,
                             const float* gg, const float* gu, const float* gd) {
    const float* srcs[6] = { ug, uu, ud, gg, gu, gd };
    const float4* s = (const float4*)srcs[blockIdx.y];
    __half2* d = (__half2*)g_W[blockIdx.y];
    const size_t N4 = (size_t)DD * II / 4;
    for (size_t i = (size_t)blockIdx.x * blockDim.x + threadIdx.x; i < N4;
         i += (size_t)gridDim.x * blockDim.x) {
        float4 v = s[i];
        d[2 * i + 0] = __floats2half2_rn(v.x, v.y);
        d[2 * i + 1] = __floats2half2_rn(v.z, v.w);
    }
}

// ---------------- kernel 3: gather + convert X ----------------------------
__global__ void gather_kernel(const float* X) {
    int e = blockIdx.y;
    int slot = blockIdx.x;
    if (slot >= g_cnt[e]) return;
    const float4* s = (const float4*)(X + (size_t)g_idx[e][slot] * DD);
    __half2* d = (__half2*)(g_Xc[e] + (size_t)slot * DD);
    for (int i = threadIdx.x; i < DD / 4; i += blockDim.x) {
        float4 v = s[i];
        d[2 * i + 0] = __floats2half2_rn(v.x, v.y);
        d[2 * i + 1] = __floats2half2_rn(v.z, v.w);
    }
}

// ---------------- GEMM config ---------------------------------------------
// 384 threads, 12 warps, warp tile 64x64 (128 f32 accums). BK=64, 3 stages.
constexpr int BK  = 64;
constexpr int BM  = 192;
constexpr int LDA = 72;          // halves per A smem row (64 + 8 pad); 144 B
constexpr int A_BYTES = BM * LDA * 2;         // 27648
// gemm1: BN=128, two B matrices (gate, up), each [64][136]
constexpr int LDB1 = 136;                     // 272 B per row
constexpr int B1_BYTES = BK * LDB1 * 2;       // 17408
constexpr int STG1 = A_BYTES + 2 * B1_BYTES;  // 62464
constexpr int SMEM1 = 3 * STG1;               // 187392
// gemm2: BN=256, one B matrix [64][264]
constexpr int LDB2 = 264;                     // 528 B per row
constexpr int B2_BYTES = BK * LDB2 * 2;       // 33792
constexpr int STG2 = A_BYTES + B2_BYTES;      // 61440
constexpr int SMEM2 = 3 * STG2;               // 184320

constexpr int MGRID = (TOK + BM - 1) / BM;    // 86

// ---------------- kernel 4: fused gate/up GEMM + SiLU ---------------------
// CTA: 192 rows x 128 H-cols. Warps 0-5 gate, 6-11 up; each warp 64x64.
__global__ __launch_bounds__(384, 1) void gemm1_kernel() {
    extern __shared__ char smem[];
    const int e = blockIdx.z;
    const int cnt = g_cnt[e];
    const int m0 = blockIdx.x * BM;
    if (m0 >= cnt) return;
    const int n0 = blockIdx.y * 128;
    const __half* A  = g_Xc[e];
    const __half* Bg = g_W[e ? 3 : 0];
    const __half* Bu = g_W[e ? 4 : 1];
    const int t = threadIdx.x;
    const int wid = t >> 5, lane = t & 31;
    const int gu = wid / 6;                  // 0 = gate, 1 = up
    const int w6 = wid % 6;
    const int wm = w6 >> 1;                  // 0..2  (64-row slab)
    const int wn = w6 & 1;                   // 0..1  (64-col slab)

    auto load_stage = [&](int kb, int st) {
        char* base = smem + st * STG1;
        #pragma unroll
        for (int i = 0; i < 4; i++) {        // A: 192 rows x 8 chunks = 1536
            int id = t + i * 384;
            int r = id >> 3, c = id & 7;
            cp16(base + r * (LDA * 2) + c * 16,
                 A + (size_t)(m0 + r) * DD + kb * BK + c * 8, (m0 + r) < cnt);
        }
        for (int id = t; id < 1024; id += 384) {   // Bg & Bu: 64 rows x 16 chunks
            int r = id >> 4, c = id & 15;
            size_t go = (size_t)(kb * BK + r) * II + n0 + c * 8;
            char* bb = base + A_BYTES + r * (LDB1 * 2) + c * 16;
            cp16(bb, Bg + go, true);
            cp16(bb + B1_BYTES, Bu + go, true);
        }
        cp_commit();
    };

    float acc[4][8][4];
    #pragma unroll
    for (int mi = 0; mi < 4; mi++)
        #pragma unroll
        for (int ni = 0; ni < 8; ni++)
            #pragma unroll
            for (int k = 0; k < 4; k++) acc[mi][ni][k] = 0.f;

    const int KB = DD / BK;   // 32
    load_stage(0, 0);
    load_stage(1, 1);

    const int lr = lane % 16, lc = (lane / 16) * 8;

    for (int kb = 0; kb < KB; kb++) {
        int st = kb % 3;
        cp_wait1();
        __syncthreads();
        if (kb + 2 < KB) load_stage(kb + 2, (kb + 2) % 3); else cp_commit();

        char* base = smem + st * STG1;
        const __half* At = (const __half*)base;
        const __half* Bt = (const __half*)(base + A_BYTES + gu * B1_BYTES);
        #pragma unroll
        for (int ks = 0; ks < 4; ks++) {
            uint32_t a[4][4];
            #pragma unroll
            for (int mi = 0; mi < 4; mi++)
                ldsm4(a[mi], At + (wm * 64 + mi * 16 + lr) * LDA + ks * 16 + lc);
            uint32_t b[4][4];
            #pragma unroll
            for (int np = 0; np < 4; np++)
                ldsm4t(b[np], Bt + (ks * 16 + lr) * LDB1 + wn * 64 + np * 16 + lc);
            #pragma unroll
            for (int mi = 0; mi < 4; mi++)
                #pragma unroll
                for (int ni = 0; ni < 8; ni++)
                    mma16816(acc[mi][ni], a[mi], &b[ni >> 1][(ni & 1) * 2]);
        }
    }

    // epilogue: gate warps stage g (f32) in smem; up warps combine + store H
    __syncthreads();
    float* stg = (float*)smem;               // 192 x 132 f32 = 101376 B
    const int r4 = lane >> 2, c2 = (lane & 3) * 2;
    if (gu == 0) {
        #pragma unroll
        for (int mi = 0; mi < 4; mi++)
            #pragma unroll
            for (int h = 0; h < 2; h++) {
                int row = wm * 64 + mi * 16 + h * 8 + r4;
                #pragma unroll
                for (int ni = 0; ni < 8; ni++) {
                    int col = wn * 64 + ni * 8 + c2;
                    stg[row * 132 + col]     = acc[mi][ni][h * 2 + 0];
                    stg[row * 132 + col + 1] = acc[mi][ni][h * 2 + 1];
                }
            }
    }
    __syncthreads();
    if (gu == 1) {
        #pragma unroll
        for (int mi = 0; mi < 4; mi++)
            #pragma unroll
            for (int h = 0; h < 2; h++) {
                int row = wm * 64 + mi * 16 + h * 8 + r4;
                int slot = m0 + row;
                if (slot < cnt) {
                    __half2* dst = (__half2*)(g_H[e] + (size_t)slot * II + n0);
                    #pragma unroll
                    for (int ni = 0; ni < 8; ni++) {
                        int col = wn * 64 + ni * 8 + c2;
                        float g0 = stg[row * 132 + col];
                        float g1 = stg[row * 132 + col + 1];
                        float u0 = acc[mi][ni][h * 2 + 0];
                        float u1 = acc[mi][ni][h * 2 + 1];
                        float h0 = g0 / (1.0f + expf(-g0)) * u0;
                        float h1 = g1 / (1.0f + expf(-g1)) * u1;
                        dst[col >> 1] = __floats2half2_rn(h0, h1);
                    }
                }
            }
    }
}

// ---------------- kernel 5: down GEMM + scatter ---------------------------
// CTA: 192 rows x 256 out-cols. 12 warps: wm=wid%3 (64-row), wn=wid/3 (64-col).
__global__ __launch_bounds__(384, 1) void gemm2_kernel(float* out) {
    extern __shared__ char smem[];
    const int e = blockIdx.z;
    const int cnt = g_cnt[e];
    const int m0 = blockIdx.x * BM;
    if (m0 >= cnt) return;
    const int n0 = blockIdx.y * 256;
    const __half* A  = g_H[e];
    const __half* Bd = g_W[e ? 5 : 2];
    const int t = threadIdx.x;
    const int wid = t >> 5, lane = t & 31;
    const int wm = wid % 3;                  // 0..2
    const int wn = wid / 3;                  // 0..3

    auto load_stage = [&](int kb, int st) {
        char* base = smem + st * STG2;
        #pragma unroll
        for (int i = 0; i < 4; i++) {        // A: 192 rows x 8 chunks = 1536
            int id = t + i * 384;
            int r = id >> 3, c = id & 7;
            cp16(base + r * (LDA * 2) + c * 16,
                 A + (size_t)(m0 + r) * II + kb * BK + c * 8, (m0 + r) < cnt);
        }
        for (int id = t; id < 2048; id += 384) {   // B: 64 rows x 32 chunks
            int r = id >> 5, c = id & 31;
            cp16(base + A_BYTES + r * (LDB2 * 2) + c * 16,
                 Bd + (size_t)(kb * BK + r) * DD + n0 + c * 8, true);
        }
        cp_commit();
    };

    float acc[4][8][4];
    #pragma unroll
    for (int mi = 0; mi < 4; mi++)
        #pragma unroll
        for (int ni = 0; ni < 8; ni++)
            #pragma unroll
            for (int k = 0; k < 4; k++) acc[mi][ni][k] = 0.f;

    const int KB = II / BK;   // 88
    load_stage(0, 0);
    load_stage(1, 1);

    const int lr = lane % 16, lc = (lane / 16) * 8;

    for (int kb = 0; kb < KB; kb++) {
        int st = kb % 3;
        cp_wait1();
        __syncthreads();
        if (kb + 2 < KB) load_stage(kb + 2, (kb + 2) % 3); else cp_commit();

        char* base = smem + st * STG2;
        const __half* At = (const __half*)base;
        const __half* Bt = (const __half*)(base + A_BYTES);
        #pragma unroll
        for (int ks = 0; ks < 4; ks++) {
            uint32_t a[4][4];
            #pragma unroll
            for (int mi = 0; mi < 4; mi++)
                ldsm4(a[mi], At + (wm * 64 + mi * 16 + lr) * LDA + ks * 16 + lc);
            uint32_t b[4][4];
            #pragma unroll
            for (int np = 0; np < 4; np++)
                ldsm4t(b[np], Bt + (ks * 16 + lr) * LDB2 + wn * 64 + np * 16 + lc);
            #pragma unroll
            for (int mi = 0; mi < 4; mi++)
                #pragma unroll
                for (int ni = 0; ni < 8; ni++)
                    mma16816(acc[mi][ni], a[mi], &b[ni >> 1][(ni & 1) * 2]);
        }
    }

    // epilogue: scatter f32 to original token rows
    const int r4 = lane >> 2, c2 = (lane & 3) * 2;
    #pragma unroll
    for (int mi = 0; mi < 4; mi++)
        #pragma unroll
        for (int h = 0; h < 2; h++) {
            int row = wm * 64 + mi * 16 + h * 8 + r4;
            int slot = m0 + row;
            if (slot < cnt) {
                int token = g_idx[e][slot];
                float2* dst = (float2*)(out + (size_t)token * DD + n0);
                #pragma unroll
                for (int ni = 0; ni < 8; ni++) {
                    int col = wn * 64 + ni * 8 + c2;
                    dst[col >> 1] = make_float2(acc[mi][ni][h * 2 + 0],
                                                acc[mi][ni][h * 2 + 1]);
                }
            }
        }
}

// ---------------- host launcher -------------------------------------------
extern "C" void kernel_launch(void* const* d_in, const int* in_sizes, int n_in,
                              void* d_out, int out_size) {
    const float* X = (const float*)d_in[0];
    const unsigned char* M = (const unsigned char*)d_in[1];
    const float* ug = (const float*)d_in[2];
    const float* uu = (const float*)d_in[3];
    const float* ud = (const float*)d_in[4];
    const float* gg = (const float*)d_in[5];
    const float* gu = (const float*)d_in[6];
    const float* gd = (const float*)d_in[7];
    float* out = (float*)d_out;

    cudaFuncSetAttribute(gemm1_kernel, cudaFuncAttributeMaxDynamicSharedMemorySize, SMEM1);
    cudaFuncSetAttribute(gemm2_kernel, cudaFuncAttributeMaxDynamicSharedMemorySize, SMEM2);

    prep_kernel<<<1, 256>>>(M);
    cvt_w_kernel<<<dim3(2048, 6), 256>>>(ug, uu, ud, gg, gu, gd);
    gather_kernel<<<dim3(TOK, 2), 128>>>(X);
    gemm1_kernel<<<dim3(MGRID, II / 128, 2), 384, SMEM1>>>();
    gemm2_kernel<<<dim3(MGRID, DD / 256, 2), 384, SMEM2>>>(out);
}

// round 10
// speedup vs baseline: 1.1523x; 1.0565x over previous
#include <cuda_runtime.h>
#include <cuda_fp16.h>
#include <cstdint>
#include <cstddef>

#define TOK 16384
#define DD  2048
#define II  5632

// ---------------- scratch (device globals: no allocation allowed) ----------
__device__ __half g_W[6][(size_t)DD * II];      // fp16 weights: gate/up (D,I), down (I,D)
__device__ __half g_Xc[2][(size_t)TOK * DD];    // gathered activations per expert
__device__ __half g_H[2][(size_t)TOK * II];     // intermediate silu(g)*u per expert
__device__ int    g_idx[2][TOK];                // compacted token indices
__device__ int    g_cnt[2];                     // counts per expert

// ---------------- helpers --------------------------------------------------
__device__ __forceinline__ uint32_t smem_u32(const void* p) {
    return (uint32_t)__cvta_generic_to_shared(p);
}
__device__ __forceinline__ void cp16(void* dst, const void* src, bool pred) {
    uint32_t d = smem_u32(dst);
    int sz = pred ? 16 : 0;
    asm volatile("cp.async.cg.shared.global [%0], [%1], 16, %2;\n"
                 :: "r"(d), "l"(src), "r"(sz));
}
// arrival (1 per thread) delivered when this thread's prior cp.asyncs complete
__device__ __forceinline__ void cpam(uint32_t mb) {
    asm volatile("cp.async.mbarrier.arrive.noinc.shared.b64 [%0];" :: "r"(mb) : "memory");
}
__device__ __forceinline__ void mbar_init(uint32_t a, uint32_t n) {
    asm volatile("mbarrier.init.shared.b64 [%0], %1;" :: "r"(a), "r"(n) : "memory");
}
__device__ __forceinline__ void mbar_arrive(uint32_t a) {
    asm volatile("mbarrier.arrive.shared.b64 _, [%0];" :: "r"(a) : "memory");
}
__device__ __forceinline__ void mbar_wait(uint32_t a, uint32_t parity) {
    asm volatile("{\n\t.reg .pred P;\n\t"
        "WL%=:\n\t"
        "mbarrier.try_wait.parity.shared.b64 P, [%0], %1;\n\t"
        "@!P bra WL%=;\n\t}" :: "r"(a), "r"(parity) : "memory");
}
__device__ __forceinline__ void ldsm4(uint32_t* r, const void* p) {
    uint32_t a = smem_u32(p);
    asm volatile("ldmatrix.sync.aligned.m8n8.x4.shared.b16 {%0,%1,%2,%3}, [%4];\n"
                 : "=r"(r[0]), "=r"(r[1]), "=r"(r[2]), "=r"(r[3]) : "r"(a));
}
__device__ __forceinline__ void ldsm4t(uint32_t* r, const void* p) {
    uint32_t a = smem_u32(p);
    asm volatile("ldmatrix.sync.aligned.m8n8.x4.trans.shared.b16 {%0,%1,%2,%3}, [%4];\n"
                 : "=r"(r[0]), "=r"(r[1]), "=r"(r[2]), "=r"(r[3]) : "r"(a));
}
__device__ __forceinline__ void mma16816(float* c, const uint32_t* a, const uint32_t* b) {
    asm volatile("mma.sync.aligned.m16n8k16.row.col.f32.f16.f16.f32 "
                 "{%0,%1,%2,%3}, {%4,%5,%6,%7}, {%8,%9}, {%0,%1,%2,%3};\n"
                 : "+f"(c[0]), "+f"(c[1]), "+f"(c[2]), "+f"(c[3])
                 : "r"(a[0]), "r"(a[1]), "r"(a[2]), "r"(a[3]), "r"(b[0]), "r"(b[1]));
}

// ---------------- kernel 1: mask decode + deterministic compaction --------
__global__ void prep_kernel(const unsigned char* mraw) {
    __shared__ int sf[4];
    __shared__ int scnt[256];
    __shared__ int soff[257];
    int t = threadIdx.x;
    if (t < 4) sf[t] = 0;
    __syncthreads();
    int f3F = 0, foff = 0, flo = 0, f3C = 0;
    for (int i = t * 64; i < t * 64 + 64; i++) {
        unsigned char b = mraw[i];
        if (b == 0x3F) f3F = 1;
        if (b == 0x3C) f3C = 1;
        if ((i & 3) && b) foff = 1;
        if (((i & 3) <= 1) && b) flo = 1;
    }
    if (f3F) atomicOr(&sf[0], 1);
    if (foff) atomicOr(&sf[1], 1);
    if (flo) atomicOr(&sf[2], 1);
    if (f3C) atomicOr(&sf[3], 1);
    __syncthreads();
    int mode;
    if (sf[0]) mode = sf[2] ? 3 : 2;
    else if (sf[3]) mode = 4;
    else if (sf[1]) mode = 0;
    else mode = 1;
    unsigned long long bits = 0;
    for (int i = 0; i < 64; i++) {
        int tok = t * 64 + i;
        bool g;
        if (mode == 0)      g = mraw[tok] != 0;
        else if (mode == 1) g = ((const int*)mraw)[tok] != 0;
        else if (mode == 2) g = ((const float*)mraw)[tok] != 0.0f;
        else                g = ((const unsigned short*)mraw)[tok] != 0;
        if (g) bits |= 1ull << i;
    }
    scnt[t] = __popcll(bits);
    __syncthreads();
    if (t == 0) {
        int a = 0;
        for (int i = 0; i < 256; i++) { soff[i] = a; a += scnt[i]; }
        g_cnt[1] = a;
        g_cnt[0] = TOK - a;
    }
    __syncthreads();
    int gp = soff[t];
    int up = t * 64 - gp;
    for (int i = 0; i < 64; i++) {
        int tok = t * 64 + i;
        if ((bits >> i) & 1) g_idx[1][gp++] = tok;
        else                 g_idx[0][up++] = tok;
    }
}

// ---------------- kernel 2: weight f32 -> f16 (same layout) ---------------
__global__ void cvt_w_kernel(const float* ug, const float* uu, const float* ud,
                             const float* gg, const float* gu, const float* gd) {
    const float* srcs[6] = { ug, uu, ud, gg, gu, gd };
    const float4* s = (const float4*)srcs[blockIdx.y];
    __half2* d = (__half2*)g_W[blockIdx.y];
    const size_t N4 = (size_t)DD * II / 4;
    for (size_t i = (size_t)blockIdx.x * blockDim.x + threadIdx.x; i < N4;
         i += (size_t)gridDim.x * blockDim.x) {
        float4 v = s[i];
        d[2 * i + 0] = __floats2half2_rn(v.x, v.y);
        d[2 * i + 1] = __floats2half2_rn(v.z, v.w);
    }
}

// ---------------- kernel 3: gather + convert X ----------------------------
__global__ void gather_kernel(const float* X) {
    int e = blockIdx.y;
    int slot = blockIdx.x;
    if (slot >= g_cnt[e]) return;
    const float4* s = (const float4*)(X + (size_t)g_idx[e][slot] * DD);
    __half2* d = (__half2*)(g_Xc[e] + (size_t)slot * DD);
    for (int i = threadIdx.x; i < DD / 4; i += blockDim.x) {
        float4 v = s[i];
        d[2 * i + 0] = __floats2half2_rn(v.x, v.y);
        d[2 * i + 1] = __floats2half2_rn(v.z, v.w);
    }
}

// ---------------- GEMM config ---------------------------------------------
// 384 threads, 12 warps, warp tile 64x64 (128 f32 accums). BK=64, 3 stages.
// mbarrier producer/consumer ring with explicit cursors (Pipeline convention).
constexpr int BK  = 64;
constexpr int BM  = 192;
constexpr int LDA = 72;          // halves per A smem row (64 + 8 pad); 144 B
constexpr int A_BYTES = BM * LDA * 2;         // 27648
constexpr int HDR = 128;                      // mbarrier block
// gemm1: BN=128, two B matrices (gate, up), each [64][136]
constexpr int LDB1 = 136;                     // 272 B per row
constexpr int B1_BYTES = BK * LDB1 * 2;       // 17408
constexpr int STG1 = A_BYTES + 2 * B1_BYTES;  // 62464
constexpr int SMEM1 = HDR + 3 * STG1;         // 187520
// gemm2: BN=256, one B matrix [64][264]
constexpr int LDB2 = 264;                     // 528 B per row
constexpr int B2_BYTES = BK * LDB2 * 2;       // 33792
constexpr int STG2 = A_BYTES + B2_BYTES;      // 61440
constexpr int SMEM2 = HDR + 3 * STG2;         // 184448

constexpr int MGRID = (TOK + BM - 1) / BM;    // 86

// ---------------- kernel 4: fused gate/up GEMM + SiLU ---------------------
// CTA: 192 rows x 128 H-cols. Warps 0-5 gate, 6-11 up; each warp 64x64.
__global__ __launch_bounds__(384, 1) void gemm1_kernel() {
    extern __shared__ char smem[];
    const int e = blockIdx.z;
    const int cnt = g_cnt[e];
    const int m0 = blockIdx.x * BM;
    if (m0 >= cnt) return;
    const int n0 = blockIdx.y * 128;
    const __half* A  = g_Xc[e];
    const __half* Bg = g_W[e ? 3 : 0];
    const __half* Bu = g_W[e ? 4 : 1];
    const int t = threadIdx.x;
    const int wid = t >> 5, lane = t & 31;
    const int gu = wid / 6;                  // 0 = gate, 1 = up
    const int w6 = wid % 6;
    const int wm = w6 >> 1;                  // 0..2  (64-row slab)
    const int wn = w6 & 1;                   // 0..1  (64-col slab)
    const uint32_t sb = smem_u32(smem);
    // full[s] = sb + s*16, empty[s] = sb + s*16 + 8

    auto load_stage = [&](int kb, int st) {
        char* base = smem + HDR + st * STG1;
        #pragma unroll
        for (int i = 0; i < 4; i++) {        // A: 192 rows x 8 chunks = 1536
            int id = t + i * 384;
            int r = id >> 3, c = id & 7;
            cp16(base + r * (LDA * 2) + c * 16,
                 A + (size_t)(m0 + r) * DD + kb * BK + c * 8, (m0 + r) < cnt);
        }
        for (int id = t; id < 1024; id += 384) {   // Bg & Bu: 64 rows x 16 chunks
            int r = id >> 4, c = id & 15;
            size_t go = (size_t)(kb * BK + r) * II + n0 + c * 8;
            char* bb = base + A_BYTES + r * (LDB1 * 2) + c * 16;
            cp16(bb, Bg + go, true);
            cp16(bb + B1_BYTES, Bu + go, true);
        }
    };

    if (t == 0)
        for (int s = 0; s < 3; s++) { mbar_init(sb + s * 16, 384); mbar_init(sb + s * 16 + 8, 384); }
    __syncthreads();

    float acc[4][8][4];
    #pragma unroll
    for (int mi = 0; mi < 4; mi++)
        #pragma unroll
        for (int ni = 0; ni < 8; ni++)
            #pragma unroll
            for (int k = 0; k < 4; k++) acc[mi][ni][k] = 0.f;

    const int KB = DD / BK;   // 32
    load_stage(0, 0); cpam(sb + 0 * 16);
    load_stage(1, 1); cpam(sb + 1 * 16);

    // producer cursor: after 2 prologue loads -> stage 2, phase 1 (flip trick)
    int pstage = 2, pphase = 1;
    int cstage = 0, cphase = 0;

    const int lr = lane % 16, lc = (lane / 16) * 8;

    for (int kb = 0; kb < KB; kb++) {
        if (kb + 2 < KB) {
            mbar_wait(sb + pstage * 16 + 8, pphase);   // stage free?
            load_stage(kb + 2, pstage);
            cpam(sb + pstage * 16);
            if (++pstage == 3) { pstage = 0; pphase ^= 1; }
        }
        mbar_wait(sb + cstage * 16, cphase);           // stage loaded?

        char* base = smem + HDR + cstage * STG1;
        const __half* At = (const __half*)base;
        const __half* Bt = (const __half*)(base + A_BYTES + gu * B1_BYTES);
        #pragma unroll
        for (int ks = 0; ks < 4; ks++) {
            uint32_t a[4][4];
            #pragma unroll
            for (int mi = 0; mi < 4; mi++)
                ldsm4(a[mi], At + (wm * 64 + mi * 16 + lr) * LDA + ks * 16 + lc);
            uint32_t b[4][4];
            #pragma unroll
            for (int np = 0; np < 4; np++)
                ldsm4t(b[np], Bt + (ks * 16 + lr) * LDB1 + wn * 64 + np * 16 + lc);
            #pragma unroll
            for (int mi = 0; mi < 4; mi++)
                #pragma unroll
                for (int ni = 0; ni < 8; ni++)
                    mma16816(acc[mi][ni], a[mi], &b[ni >> 1][(ni & 1) * 2]);
        }
        mbar_arrive(sb + cstage * 16 + 8);             // done reading stage
        if (++cstage == 3) { cstage = 0; cphase ^= 1; }
    }

    // epilogue: gate warps stage g (f32) in smem; up warps combine + store H
    __syncthreads();
    float* stg = (float*)smem;               // 192 x 132 f32 = 101376 B
    const int r4 = lane >> 2, c2 = (lane & 3) * 2;
    if (gu == 0) {
        #pragma unroll
        for (int mi = 0; mi < 4; mi++)
            #pragma unroll
            for (int h = 0; h < 2; h++) {
                int row = wm * 64 + mi * 16 + h * 8 + r4;
                #pragma unroll
                for (int ni = 0; ni < 8; ni++) {
                    int col = wn * 64 + ni * 8 + c2;
                    stg[row * 132 + col]     = acc[mi][ni][h * 2 + 0];
                    stg[row * 132 + col + 1] = acc[mi][ni][h * 2 + 1];
                }
            }
    }
    __syncthreads();
    if (gu == 1) {
        #pragma unroll
        for (int mi = 0; mi < 4; mi++)
            #pragma unroll
            for (int h = 0; h < 2; h++) {
                int row = wm * 64 + mi * 16 + h * 8 + r4;
                int slot = m0 + row;
                if (slot < cnt) {
                    __half2* dst = (__half2*)(g_H[e] + (size_t)slot * II + n0);
                    #pragma unroll
                    for (int ni = 0; ni < 8; ni++) {
                        int col = wn * 64 + ni * 8 + c2;
                        float g0 = stg[row * 132 + col];
                        float g1 = stg[row * 132 + col + 1];
                        float u0 = acc[mi][ni][h * 2 + 0];
                        float u1 = acc[mi][ni][h * 2 + 1];
                        float h0 = g0 / (1.0f + expf(-g0)) * u0;
                        float h1 = g1 / (1.0f + expf(-g1)) * u1;
                        dst[col >> 1] = __floats2half2_rn(h0, h1);
                    }
                }
            }
    }
}

// ---------------- kernel 5: down GEMM + scatter ---------------------------
// CTA: 192 rows x 256 out-cols. 12 warps: wm=wid%3 (64-row), wn=wid/3 (64-col).
__global__ __launch_bounds__(384, 1) void gemm2_kernel(float* out) {
    extern __shared__ char smem[];
    const int e = blockIdx.z;
    const int cnt = g_cnt[e];
    const int m0 = blockIdx.x * BM;
    if (m0 >= cnt) return;
    const int n0 = blockIdx.y * 256;
    const __half* A  = g_H[e];
    const __half* Bd = g_W[e ? 5 : 2];
    const int t = threadIdx.x;
    const int wid = t >> 5, lane = t & 31;
    const int wm = wid % 3;                  // 0..2
    const int wn = wid / 3;                  // 0..3
    const uint32_t sb = smem_u32(smem);

    auto load_stage = [&](int kb, int st) {
        char* base = smem + HDR + st * STG2;
        #pragma unroll
        for (int i = 0; i < 4; i++) {        // A: 192 rows x 8 chunks = 1536
            int id = t + i * 384;
            int r = id >> 3, c = id & 7;
            cp16(base + r * (LDA * 2) + c * 16,
                 A + (size_t)(m0 + r) * II + kb * BK + c * 8, (m0 + r) < cnt);
        }
        for (int id = t; id < 2048; id += 384) {   // B: 64 rows x 32 chunks
            int r = id >> 5, c = id & 31;
            cp16(base + A_BYTES + r * (LDB2 * 2) + c * 16,
                 Bd + (size_t)(kb * BK + r) * DD + n0 + c * 8, true);
        }
    };

    if (t == 0)
        for (int s = 0; s < 3; s++) { mbar_init(sb + s * 16, 384); mbar_init(sb + s * 16 + 8, 384); }
    __syncthreads();

    float acc[4][8][4];
    #pragma unroll
    for (int mi = 0; mi < 4; mi++)
        #pragma unroll
        for (int ni = 0; ni < 8; ni++)
            #pragma unroll
            for (int k = 0; k < 4; k++) acc[mi][ni][k] = 0.f;

    const int KB = II / BK;   // 88
    load_stage(0, 0); cpam(sb + 0 * 16);
    load_stage(1, 1); cpam(sb + 1 * 16);

    int pstage = 2, pphase = 1;
    int cstage = 0, cphase = 0;

    const int lr = lane % 16, lc = (lane / 16) * 8;

    for (int kb = 0; kb < KB; kb++) {
        if (kb + 2 < KB) {
            mbar_wait(sb + pstage * 16 + 8, pphase);
            load_stage(kb + 2, pstage);
            cpam(sb + pstage * 16);
            if (++pstage == 3) { pstage = 0; pphase ^= 1; }
        }
        mbar_wait(sb + cstage * 16, cphase);

        char* base = smem + HDR + cstage * STG2;
        const __half* At = (const __half*)base;
        const __half* Bt = (const __half*)(base + A_BYTES);
        #pragma unroll
        for (int ks = 0; ks < 4; ks++) {
            uint32_t a[4][4];
            #pragma unroll
            for (int mi = 0; mi < 4; mi++)
                ldsm4(a[mi], At + (wm * 64 + mi * 16 + lr) * LDA + ks * 16 + lc);
            uint32_t b[4][4];
            #pragma unroll
            for (int np = 0; np < 4; np++)
                ldsm4t(b[np], Bt + (ks * 16 + lr) * LDB2 + wn * 64 + np * 16 + lc);
            #pragma unroll
            for (int mi = 0; mi < 4; mi++)
                #pragma unroll
                for (int ni = 0; ni < 8; ni++)
                    mma16816(acc[mi][ni], a[mi], &b[ni >> 1][(ni & 1) * 2]);
        }
        mbar_arrive(sb + cstage * 16 + 8);
        if (++cstage == 3) { cstage = 0; cphase ^= 1; }
    }

    // epilogue: scatter f32 to original token rows
    const int r4 = lane >> 2, c2 = (lane & 3) * 2;
    #pragma unroll
    for (int mi = 0; mi < 4; mi++)
        #pragma unroll
        for (int h = 0; h < 2; h++) {
            int row = wm * 64 + mi * 16 + h * 8 + r4;
            int slot = m0 + row;
            if (slot < cnt) {
                int token = g_idx[e][slot];
                float2* dst = (float2*)(out + (size_t)token * DD + n0);
                #pragma unroll
                for (int ni = 0; ni < 8; ni++) {
                    int col = wn * 64 + ni * 8 + c2;
                    dst[col >> 1] = make_float2(acc[mi][ni][h * 2 + 0],
                                                acc[mi][ni][h * 2 + 1]);
                }
            }
        }
}

// ---------------- host launcher -------------------------------------------
extern "C" void kernel_launch(void* const* d_in, const int* in_sizes, int n_in,
                              void* d_out, int out_size) {
    const float* X = (const float*)d_in[0];
    const unsigned char* M = (const unsigned char*)d_in[1];
    const float* ug = (const float*)d_in[2];
    const float* uu = (const float*)d_in[3];
    const float* ud = (const float*)d_in[4];
    const float* gg = (const float*)d_in[5];
    const float* gu = (const float*)d_in[6];
    const float* gd = (const float*)d_in[7];
    float* out = (float*)d_out;

    cudaFuncSetAttribute(gemm1_kernel, cudaFuncAttributeMaxDynamicSharedMemorySize, SMEM1);
    cudaFuncSetAttribute(gemm2_kernel, cudaFuncAttributeMaxDynamicSharedMemorySize, SMEM2);

    prep_kernel<<<1, 256>>>(M);
    cvt_w_kernel<<<dim3(2048, 6), 256>>>(ug, uu, ud, gg, gu, gd);
    gather_kernel<<<dim3(TOK, 2), 128>>>(X);
    gemm1_kernel<<<dim3(MGRID, II / 128, 2), 384, SMEM1>>>();
    gemm2_kernel<<<dim3(MGRID, DD / 256, 2), 384, SMEM2>>>(out);
}

// round 11
// speedup vs baseline: 1.3341x; 1.1577x over previous
#include <cuda_runtime.h>
#include <cuda_fp16.h>
#include <cstdint>
#include <cstddef>

#define TOK 16384
#define DD  2048
#define II  5632

// ---------------- scratch (device globals: no allocation allowed) ----------
__device__ __half g_W[6][(size_t)DD * II];      // fp16 weights: gate/up (D,I), down (I,D)
__device__ __half g_Xc[2][(size_t)TOK * DD];    // gathered activations per expert
__device__ __half g_H[2][(size_t)TOK * II];     // intermediate silu(g)*u per expert
__device__ int    g_idx[2][TOK];                // compacted token indices
__device__ int    g_cnt[2];                     // counts per expert

// ---------------- helpers --------------------------------------------------
__device__ __forceinline__ uint32_t smem_u32(const void* p) {
    return (uint32_t)__cvta_generic_to_shared(p);
}
__device__ __forceinline__ void cp16(void* dst, const void* src, bool pred) {
    uint32_t d = smem_u32(dst);
    int sz = pred ? 16 : 0;
    asm volatile("cp.async.cg.shared.global [%0], [%1], 16, %2;\n"
                 :: "r"(d), "l"(src), "r"(sz));
}
// arrival (1 per thread) delivered when this thread's prior cp.asyncs complete
__device__ __forceinline__ void cpam(uint32_t mb) {
    asm volatile("cp.async.mbarrier.arrive.noinc.shared.b64 [%0];" :: "r"(mb) : "memory");
}
__device__ __forceinline__ void mbar_init(uint32_t a, uint32_t n) {
    asm volatile("mbarrier.init.shared.b64 [%0], %1;" :: "r"(a), "r"(n) : "memory");
}
__device__ __forceinline__ void mbar_arrive(uint32_t a) {
    asm volatile("mbarrier.arrive.shared.b64 _, [%0];" :: "r"(a) : "memory");
}
__device__ __forceinline__ void mbar_wait(uint32_t a, uint32_t parity) {
    asm volatile("{\n\t.reg .pred P;\n\t"
        "WL%=:\n\t"
        "mbarrier.try_wait.parity.shared.b64 P, [%0], %1;\n\t"
        "@!P bra WL%=;\n\t}" :: "r"(a), "r"(parity) : "memory");
}
__device__ __forceinline__ void ldsm4(uint32_t* r, const void* p) {
    uint32_t a = smem_u32(p);
    asm volatile("ldmatrix.sync.aligned.m8n8.x4.shared.b16 {%0,%1,%2,%3}, [%4];\n"
                 : "=r"(r[0]), "=r"(r[1]), "=r"(r[2]), "=r"(r[3]) : "r"(a));
}
__device__ __forceinline__ void ldsm4t(uint32_t* r, const void* p) {
    uint32_t a = smem_u32(p);
    asm volatile("ldmatrix.sync.aligned.m8n8.x4.trans.shared.b16 {%0,%1,%2,%3}, [%4];\n"
                 : "=r"(r[0]), "=r"(r[1]), "=r"(r[2]), "=r"(r[3]) : "r"(a));
}
__device__ __forceinline__ void mma16816(float* c, const uint32_t* a, const uint32_t* b) {
    asm volatile("mma.sync.aligned.m16n8k16.row.col.f32.f16.f16.f32 "
                 "{%0,%1,%2,%3}, {%4,%5,%6,%7}, {%8,%9}, {%0,%1,%2,%3};\n"
                 : "+f"(c[0]), "+f"(c[1]), "+f"(c[2]), "+f"(c[3])
                 : "r"(a[0]), "r"(a[1]), "r"(a[2]), "r"(a[3]), "r"(b[0]), "r"(b[1]));
}

// ---------------- kernel 1: mask decode + deterministic compaction --------
__global__ void prep_kernel(const unsigned char* mraw) {
    __shared__ int sf[4];
    __shared__ int scnt[256];
    __shared__ int soff[257];
    int t = threadIdx.x;
    if (t < 4) sf[t] = 0;
    __syncthreads();
    int f3F = 0, foff = 0, flo = 0, f3C = 0;
    for (int i = t * 64; i < t * 64 + 64; i++) {
        unsigned char b = mraw[i];
        if (b == 0x3F) f3F = 1;
        if (b == 0x3C) f3C = 1;
        if ((i & 3) && b) foff = 1;
        if (((i & 3) <= 1) && b) flo = 1;
    }
    if (f3F) atomicOr(&sf[0], 1);
    if (foff) atomicOr(&sf[1], 1);
    if (flo) atomicOr(&sf[2], 1);
    if (f3C) atomicOr(&sf[3], 1);
    __syncthreads();
    int mode;
    if (sf[0]) mode = sf[2] ? 3 : 2;
    else if (sf[3]) mode = 4;
    else if (sf[1]) mode = 0;
    else mode = 1;
    unsigned long long bits = 0;
    for (int i = 0; i < 64; i++) {
        int tok = t * 64 + i;
        bool g;
        if (mode == 0)      g = mraw[tok] != 0;
        else if (mode == 1) g = ((const int*)mraw)[tok] != 0;
        else if (mode == 2) g = ((const float*)mraw)[tok] != 0.0f;
        else                g = ((const unsigned short*)mraw)[tok] != 0;
        if (g) bits |= 1ull << i;
    }
    scnt[t] = __popcll(bits);
    __syncthreads();
    if (t == 0) {
        int a = 0;
        for (int i = 0; i < 256; i++) { soff[i] = a; a += scnt[i]; }
        g_cnt[1] = a;
        g_cnt[0] = TOK - a;
    }
    __syncthreads();
    int gp = soff[t];
    int up = t * 64 - gp;
    for (int i = 0; i < 64; i++) {
        int tok = t * 64 + i;
        if ((bits >> i) & 1) g_idx[1][gp++] = tok;
        else                 g_idx[0][up++] = tok;
    }
}

// ---------------- kernel 2: weight f32 -> f16 (same layout) ---------------
__global__ void cvt_w_kernel(const float* ug, const float* uu, const float* ud,
                             const float* gg, const float* gu, const float* gd) {
    const float* srcs[6] = { ug, uu, ud, gg, gu, gd };
    const float4* s = (const float4*)srcs[blockIdx.y];
    __half2* d = (__half2*)g_W[blockIdx.y];
    const size_t N4 = (size_t)DD * II / 4;
    for (size_t i = (size_t)blockIdx.x * blockDim.x + threadIdx.x; i < N4;
         i += (size_t)gridDim.x * blockDim.x) {
        float4 v = s[i];
        d[2 * i + 0] = __floats2half2_rn(v.x, v.y);
        d[2 * i + 1] = __floats2half2_rn(v.z, v.w);
    }
}

// ---------------- kernel 3: gather + convert X ----------------------------
__global__ void gather_kernel(const float* X) {
    int e = blockIdx.y;
    int slot = blockIdx.x;
    if (slot >= g_cnt[e]) return;
    const float4* s = (const float4*)(X + (size_t)g_idx[e][slot] * DD);
    __half2* d = (__half2*)(g_Xc[e] + (size_t)slot * DD);
    for (int i = threadIdx.x; i < DD / 4; i += blockDim.x) {
        float4 v = s[i];
        d[2 * i + 0] = __floats2half2_rn(v.x, v.y);
        d[2 * i + 1] = __floats2half2_rn(v.z, v.w);
    }
}

// ---------------- GEMM config ---------------------------------------------
// 384 threads, 12 warps, warp tile 64x64 (128 f32 accums). BK=64, 3 stages.
// mbarrier ring, CONSUME-FIRST iteration order (mma before the load rendezvous).
constexpr int BK  = 64;
constexpr int BM  = 192;
constexpr int LDA = 72;          // halves per A smem row (64 + 8 pad); 144 B
constexpr int A_BYTES = BM * LDA * 2;         // 27648
constexpr int HDR = 128;                      // mbarrier block
// gemm1: BN=128, two B matrices (gate, up), each [64][136]
constexpr int LDB1 = 136;                     // 272 B per row
constexpr int B1_BYTES = BK * LDB1 * 2;       // 17408
constexpr int STG1 = A_BYTES + 2 * B1_BYTES;  // 62464
constexpr int SMEM1 = HDR + 3 * STG1;         // 187520
// gemm2: BN=256, one B matrix [64][264]
constexpr int LDB2 = 264;                     // 528 B per row
constexpr int B2_BYTES = BK * LDB2 * 2;       // 33792
constexpr int STG2 = A_BYTES + B2_BYTES;      // 61440
constexpr int SMEM2 = HDR + 3 * STG2;         // 184448

constexpr int MGRID = (TOK + BM - 1) / BM;    // 86

// ---------------- kernel 4: fused gate/up GEMM + SiLU ---------------------
// CTA: 192 rows x 128 H-cols. Warps 0-5 gate, 6-11 up; each warp 64x64.
__global__ __launch_bounds__(384, 1) void gemm1_kernel() {
    extern __shared__ char smem[];
    const int e = blockIdx.z;
    const int cnt = g_cnt[e];
    const int m0 = blockIdx.x * BM;
    if (m0 >= cnt) return;
    const int n0 = blockIdx.y * 128;
    const __half* A  = g_Xc[e];
    const __half* Bg = g_W[e ? 3 : 0];
    const __half* Bu = g_W[e ? 4 : 1];
    const int t = threadIdx.x;
    const int wid = t >> 5, lane = t & 31;
    const int gu = wid / 6;                  // 0 = gate, 1 = up
    const int w6 = wid % 6;
    const int wm = w6 >> 1;                  // 0..2  (64-row slab)
    const int wn = w6 & 1;                   // 0..1  (64-col slab)
    const uint32_t sb = smem_u32(smem);
    // full[s] = sb + s*16, empty[s] = sb + s*16 + 8

    auto load_stage = [&](int kb, int st) {
        char* base = smem + HDR + st * STG1;
        #pragma unroll
        for (int i = 0; i < 4; i++) {        // A: 192 rows x 8 chunks = 1536
            int id = t + i * 384;
            int r = id >> 3, c = id & 7;
            cp16(base + r * (LDA * 2) + c * 16,
                 A + (size_t)(m0 + r) * DD + kb * BK + c * 8, (m0 + r) < cnt);
        }
        for (int id = t; id < 1024; id += 384) {   // Bg & Bu: 64 rows x 16 chunks
            int r = id >> 4, c = id & 15;
            size_t go = (size_t)(kb * BK + r) * II + n0 + c * 8;
            char* bb = base + A_BYTES + r * (LDB1 * 2) + c * 16;
            cp16(bb, Bg + go, true);
            cp16(bb + B1_BYTES, Bu + go, true);
        }
    };

    if (t == 0)
        for (int s = 0; s < 3; s++) { mbar_init(sb + s * 16, 384); mbar_init(sb + s * 16 + 8, 384); }
    __syncthreads();

    float acc[4][8][4];
    #pragma unroll
    for (int mi = 0; mi < 4; mi++)
        #pragma unroll
        for (int ni = 0; ni < 8; ni++)
            #pragma unroll
            for (int k = 0; k < 4; k++) acc[mi][ni][k] = 0.f;

    const int KB = DD / BK;   // 32
    load_stage(0, 0); cpam(sb + 0 * 16);
    load_stage(1, 1); cpam(sb + 1 * 16);

    // producer cursor: after 2 prologue loads -> stage 2, phase 1 (flip trick)
    int pstage = 2, pphase = 1;
    int cstage = 0, cphase = 0;

    const int lr = lane % 16, lc = (lane / 16) * 8;

    for (int kb = 0; kb < KB; kb++) {
        // ---- consume kb FIRST (no CTA rendezvous before compute) ----
        mbar_wait(sb + cstage * 16, cphase);           // stage loaded?

        char* base = smem + HDR + cstage * STG1;
        const __half* At = (const __half*)base;
        const __half* Bt = (const __half*)(base + A_BYTES + gu * B1_BYTES);
        #pragma unroll
        for (int ks = 0; ks < 4; ks++) {
            uint32_t a[4][4];
            #pragma unroll
            for (int mi = 0; mi < 4; mi++)
                ldsm4(a[mi], At + (wm * 64 + mi * 16 + lr) * LDA + ks * 16 + lc);
            uint32_t b[4][4];
            #pragma unroll
            for (int np = 0; np < 4; np++)
                ldsm4t(b[np], Bt + (ks * 16 + lr) * LDB1 + wn * 64 + np * 16 + lc);
            #pragma unroll
            for (int mi = 0; mi < 4; mi++)
                #pragma unroll
                for (int ni = 0; ni < 8; ni++)
                    mma16816(acc[mi][ni], a[mi], &b[ni >> 1][(ni & 1) * 2]);
        }
        mbar_arrive(sb + cstage * 16 + 8);             // done reading stage
        if (++cstage == 3) { cstage = 0; cphase ^= 1; }

        // ---- then produce kb+2 (rendezvous overlaps other warps' mma) ----
        if (kb + 2 < KB) {
            mbar_wait(sb + pstage * 16 + 8, pphase);   // stage free?
            load_stage(kb + 2, pstage);
            cpam(sb + pstage * 16);
            if (++pstage == 3) { pstage = 0; pphase ^= 1; }
        }
    }

    // epilogue: gate warps stage g (f32) in smem; up warps combine + store H
    __syncthreads();
    float* stg = (float*)smem;               // 192 x 132 f32 = 101376 B
    const int r4 = lane >> 2, c2 = (lane & 3) * 2;
    if (gu == 0) {
        #pragma unroll
        for (int mi = 0; mi < 4; mi++)
            #pragma unroll
            for (int h = 0; h < 2; h++) {
                int row = wm * 64 + mi * 16 + h * 8 + r4;
                #pragma unroll
                for (int ni = 0; ni < 8; ni++) {
                    int col = wn * 64 + ni * 8 + c2;
                    stg[row * 132 + col]     = acc[mi][ni][h * 2 + 0];
                    stg[row * 132 + col + 1] = acc[mi][ni][h * 2 + 1];
                }
            }
    }
    __syncthreads();
    if (gu == 1) {
        #pragma unroll
        for (int mi = 0; mi < 4; mi++)
            #pragma unroll
            for (int h = 0; h < 2; h++) {
                int row = wm * 64 + mi * 16 + h * 8 + r4;
                int slot = m0 + row;
                if (slot < cnt) {
                    __half2* dst = (__half2*)(g_H[e] + (size_t)slot * II + n0);
                    #pragma unroll
                    for (int ni = 0; ni < 8; ni++) {
                        int col = wn * 64 + ni * 8 + c2;
                        float g0 = stg[row * 132 + col];
                        float g1 = stg[row * 132 + col + 1];
                        float u0 = acc[mi][ni][h * 2 + 0];
                        float u1 = acc[mi][ni][h * 2 + 1];
                        float h0 = g0 / (1.0f + __expf(-g0)) * u0;
                        float h1 = g1 / (1.0f + __expf(-g1)) * u1;
                        dst[col >> 1] = __floats2half2_rn(h0, h1);
                    }
                }
            }
    }
}

// ---------------- kernel 5: down GEMM + scatter ---------------------------
// CTA: 192 rows x 256 out-cols. 12 warps: wm=wid%3 (64-row), wn=wid/3 (64-col).
__global__ __launch_bounds__(384, 1) void gemm2_kernel(float* out) {
    extern __shared__ char smem[];
    const int e = blockIdx.z;
    const int cnt = g_cnt[e];
    const int m0 = blockIdx.x * BM;
    if (m0 >= cnt) return;
    const int n0 = blockIdx.y * 256;
    const __half* A  = g_H[e];
    const __half* Bd = g_W[e ? 5 : 2];
    const int t = threadIdx.x;
    const int wid = t >> 5, lane = t & 31;
    const int wm = wid % 3;                  // 0..2
    const int wn = wid / 3;                  // 0..3
    const uint32_t sb = smem_u32(smem);

    auto load_stage = [&](int kb, int st) {
        char* base = smem + HDR + st * STG2;
        #pragma unroll
        for (int i = 0; i < 4; i++) {        // A: 192 rows x 8 chunks = 1536
            int id = t + i * 384;
            int r = id >> 3, c = id & 7;
            cp16(base + r * (LDA * 2) + c * 16,
                 A + (size_t)(m0 + r) * II + kb * BK + c * 8, (m0 + r) < cnt);
        }
        for (int id = t; id < 2048; id += 384) {   // B: 64 rows x 32 chunks
            int r = id >> 5, c = id & 31;
            cp16(base + A_BYTES + r * (LDB2 * 2) + c * 16,
                 Bd + (size_t)(kb * BK + r) * DD + n0 + c * 8, true);
        }
    };

    if (t == 0)
        for (int s = 0; s < 3; s++) { mbar_init(sb + s * 16, 384); mbar_init(sb + s * 16 + 8, 384); }
    __syncthreads();

    float acc[4][8][4];
    #pragma unroll
    for (int mi = 0; mi < 4; mi++)
        #pragma unroll
        for (int ni = 0; ni < 8; ni++)
            #pragma unroll
            for (int k = 0; k < 4; k++) acc[mi][ni][k] = 0.f;

    const int KB = II / BK;   // 88
    load_stage(0, 0); cpam(sb + 0 * 16);
    load_stage(1, 1); cpam(sb + 1 * 16);

    int pstage = 2, pphase = 1;
    int cstage = 0, cphase = 0;

    const int lr = lane % 16, lc = (lane / 16) * 8;

    for (int kb = 0; kb < KB; kb++) {
        // ---- consume kb FIRST ----
        mbar_wait(sb + cstage * 16, cphase);

        char* base = smem + HDR + cstage * STG2;
        const __half* At = (const __half*)base;
        const __half* Bt = (const __half*)(base + A_BYTES);
        #pragma unroll
        for (int ks = 0; ks < 4; ks++) {
            uint32_t a[4][4];
            #pragma unroll
            for (int mi = 0; mi < 4; mi++)
                ldsm4(a[mi], At + (wm * 64 + mi * 16 + lr) * LDA + ks * 16 + lc);
            uint32_t b[4][4];
            #pragma unroll
            for (int np = 0; np < 4; np++)
                ldsm4t(b[np], Bt + (ks * 16 + lr) * LDB2 + wn * 64 + np * 16 + lc);
            #pragma unroll
            for (int mi = 0; mi < 4; mi++)
                #pragma unroll
                for (int ni = 0; ni < 8; ni++)
                    mma16816(acc[mi][ni], a[mi], &b[ni >> 1][(ni & 1) * 2]);
        }
        mbar_arrive(sb + cstage * 16 + 8);
        if (++cstage == 3) { cstage = 0; cphase ^= 1; }

        // ---- then produce kb+2 ----
        if (kb + 2 < KB) {
            mbar_wait(sb + pstage * 16 + 8, pphase);
            load_stage(kb + 2, pstage);
            cpam(sb + pstage * 16);
            if (++pstage == 3) { pstage = 0; pphase ^= 1; }
        }
    }

    // epilogue: scatter f32 to original token rows
    const int r4 = lane >> 2, c2 = (lane & 3) * 2;
    #pragma unroll
    for (int mi = 0; mi < 4; mi++)
        #pragma unroll
        for (int h = 0; h < 2; h++) {
            int row = wm * 64 + mi * 16 + h * 8 + r4;
            int slot = m0 + row;
            if (slot < cnt) {
                int token = g_idx[e][slot];
                float2* dst = (float2*)(out + (size_t)token * DD + n0);
                #pragma unroll
                for (int ni = 0; ni < 8; ni++) {
                    int col = wn * 64 + ni * 8 + c2;
                    dst[col >> 1] = make_float2(acc[mi][ni][h * 2 + 0],
                                                acc[mi][ni][h * 2 + 1]);
                }
            }
        }
}

// ---------------- host launcher -------------------------------------------
extern "C" void kernel_launch(void* const* d_in, const int* in_sizes, int n_in,
                              void* d_out, int out_size) {
    const float* X = (const float*)d_in[0];
    const unsigned char* M = (const unsigned char*)d_in[1];
    const float* ug = (const float*)d_in[2];
    const float* uu = (const float*)d_in[3];
    const float* ud = (const float*)d_in[4];
    const float* gg = (const float*)d_in[5];
    const float* gu = (const float*)d_in[6];
    const float* gd = (const float*)d_in[7];
    float* out = (float*)d_out;

    cudaFuncSetAttribute(gemm1_kernel, cudaFuncAttributeMaxDynamicSharedMemorySize, SMEM1);
    cudaFuncSetAttribute(gemm2_kernel, cudaFuncAttributeMaxDynamicSharedMemorySize, SMEM2);

    prep_kernel<<<1, 256>>>(M);
    cvt_w_kernel<<<dim3(2048, 6), 256>>>(ug, uu, ud, gg, gu, gd);
    gather_kernel<<<dim3(TOK, 2), 128>>>(X);
    gemm1_kernel<<<dim3(MGRID, II / 128, 2), 384, SMEM1>>>();
    gemm2_kernel<<<dim3(MGRID, DD / 256, 2), 384, SMEM2>>>(out);
}